// round 17
// baseline (speedup 1.0000x reference)
#include <cuda_runtime.h>
#include <cuda_fp16.h>
#include <cstdint>

#define KDIM 4096
#define BK 64
#define NKB (KDIM / BK)        // 64
#define A_BYTES 8192
#define B_BYTES 16384
#define STG_BYTES (A_BYTES + B_BYTES)   // 24576
#define SMEM_BYTES (3 * STG_BYTES)      // 73728
#define NCTA 256
#define CONV_AHEAD 4

// ---- scratch (static device arrays; zero-initialized at module load) ----
__device__ __half g_xh[512 * 4096];          // A[m][k]
__device__ __half g_wh[4096ull * 4096];      // B[n][k]
__device__ int    g_cnt[NKB];                // per-chunk arrival counters
__device__ int    g_done;                    // end-of-kernel rendezvous

__device__ __forceinline__ uint32_t smem_u32(const void* p) {
    uint32_t a;
    asm("{ .reg .u64 t; cvta.to.shared.u64 t, %1; cvt.u32.u64 %0, t; }" : "=r"(a) : "l"(p));
    return a;
}
__device__ __forceinline__ void cp16(uint32_t dst, const void* src) {
    asm volatile("cp.async.cg.shared.global [%0], [%1], 16;" :: "r"(dst), "l"(src));
}
__device__ __forceinline__ void ldsm_x4(uint32_t* r, uint32_t addr) {
    asm volatile("ldmatrix.sync.aligned.m8n8.x4.shared.b16 {%0,%1,%2,%3}, [%4];"
                 : "=r"(r[0]), "=r"(r[1]), "=r"(r[2]), "=r"(r[3]) : "r"(addr));
}
__device__ __forceinline__ void mma_f16(float* d, const uint32_t* a, const uint32_t* b) {
    asm volatile(
        "mma.sync.aligned.m16n8k16.row.col.f32.f16.f16.f32 "
        "{%0,%1,%2,%3}, {%4,%5,%6,%7}, {%8,%9}, {%0,%1,%2,%3};"
        : "+f"(d[0]), "+f"(d[1]), "+f"(d[2]), "+f"(d[3])
        : "r"(a[0]), "r"(a[1]), "r"(a[2]), "r"(a[3]),
          "r"(b[0]), "r"(b[1]));
}

// Convert this CTA's share of chunk c: w -> g_wh (k-major) and x -> g_xh.
// CTA r owns i (and m) in {2r, 2r+1}. 128 threads = (i_l, j_l, u) = 2x8x8.
__device__ __forceinline__ void convert_chunk(const float* __restrict__ w,
                                              const float* __restrict__ x,
                                              int c, int r, int tid)
{
    const int i_l = tid >> 6, j_l = (tid >> 3) & 7, u = tid & 7;
    const int i = 2 * r + i_l;
    const int j = c * 8 + j_l;
    // loads: w[i][j][p=u][q=0..8) -> 32B contiguous per thread
    const float* src = w + (size_t)i * 32768 + j * 64 + u * 8;
    const float4 qa = *reinterpret_cast<const float4*>(src);
    const float4 qb = *reinterpret_cast<const float4*>(src + 4);
    __half h[8];
    h[0] = __float2half_rn(qa.x); h[1] = __float2half_rn(qa.y);
    h[2] = __float2half_rn(qa.z); h[3] = __float2half_rn(qa.w);
    h[4] = __float2half_rn(qb.x); h[5] = __float2half_rn(qb.y);
    h[6] = __float2half_rn(qb.z); h[7] = __float2half_rn(qb.w);
    // stores: g_wh[n=i*8+q][k=j*8+u]; warp covers 64B contiguous per q
    __half* dst = g_wh + (size_t)(i * 8) * 4096 + j * 8 + u;
    #pragma unroll
    for (int q = 0; q < 8; ++q)
        dst[(size_t)q * 4096] = h[q];
    // x: threads 0..31 convert x[m in {2r,2r+1}][c*64..c*64+64)
    if (tid < 32) {
        const int m_l = tid >> 4, kq = tid & 15;
        const float4 v = *reinterpret_cast<const float4*>(
            x + (size_t)(2 * r + m_l) * KDIM + c * 64 + kq * 4);
        __half2 lo = __floats2half2_rn(v.x, v.y);
        __half2 hi = __floats2half2_rn(v.z, v.w);
        uint2 pk = make_uint2(*reinterpret_cast<uint32_t*>(&lo),
                              *reinterpret_cast<uint32_t*>(&hi));
        *reinterpret_cast<uint2*>(
            g_xh + (size_t)(2 * r + m_l) * KDIM + c * 64 + kq * 4) = pk;
    }
}

__global__ __launch_bounds__(128, 3)
void octonion_fused(const float* __restrict__ x, const float* __restrict__ w,
                    const float* __restrict__ bias, float* __restrict__ out)
{
    extern __shared__ char smem[];
    const uint32_t sbase = smem_u32(smem);

    const int tid  = threadIdx.x;
    const int lane = tid & 31;
    const int wn   = tid >> 5;
    const int row0 = blockIdx.y * 64;
    const int col0 = blockIdx.x * 128;
    const int r    = blockIdx.y * 32 + blockIdx.x;   // CTA linear id, 0..255

    // ---- GEMM loader descriptors ----
    const int lr = tid >> 3;
    const int lu = tid & 7;
    const __half* aSrc = g_xh + (size_t)(row0 + lr) * KDIM + lu * 8;
    const __half* bSrc = g_wh + (size_t)(col0 + lr) * KDIM + lu * 8;
    uint32_t dOff[8];
    #pragma unroll
    for (int i = 0; i < 8; ++i) {
        const int rr = lr + 16 * i;
        dOff[i] = (uint32_t)((rr & 63) * 128 + (((uint32_t)lu ^ (rr & 7)) << 4));
    }

    const int ubit = lane >> 4;
    uint32_t swx[4];
    #pragma unroll
    for (int ks = 0; ks < 4; ++ks)
        swx[ks] = (uint32_t)(((2 * ks + ubit) ^ (lane & 7)) << 4);
    const uint32_t aBase = (uint32_t)((lane & 15) * 128);
    const uint32_t bBase = A_BYTES + (uint32_t)((wn * 32 + (lane & 15)) * 128);

    float acc[4][4][4];
    #pragma unroll
    for (int i = 0; i < 4; ++i)
        #pragma unroll
        for (int j = 0; j < 4; ++j)
            #pragma unroll
            for (int rg = 0; rg < 4; ++rg)
                acc[i][j][rg] = 0.0f;

    volatile int* vcnt = g_cnt;

    // ---- prologue: convert chunks 0..3, publish, wait 0..1, prefetch 0..1 ----
    #pragma unroll
    for (int c = 0; c < CONV_AHEAD; ++c)
        convert_chunk(w, x, c, r, tid);
    __threadfence();
    __syncthreads();
    if (tid == 0) {
        #pragma unroll
        for (int c = 0; c < CONV_AHEAD; ++c)
            atomicAdd(&g_cnt[c], 1);
        while (vcnt[0] < NCTA) { }
        while (vcnt[1] < NCTA) { }
    }
    __syncthreads();
    __threadfence();

    #pragma unroll
    for (int s = 0; s < 2; ++s) {
        const uint32_t so = sbase + s * STG_BYTES;
        #pragma unroll
        for (int i = 0; i < 4; ++i)
            cp16(so + dOff[i], aSrc + (size_t)(s * BK) + (size_t)(16 * i) * KDIM);
        #pragma unroll
        for (int i = 0; i < 8; ++i)
            cp16(so + A_BYTES + dOff[i] + (uint32_t)(i >> 2) * 8192,
                 bSrc + (size_t)(s * BK) + (size_t)(16 * i) * KDIM);
        asm volatile("cp.async.commit_group;" ::: "memory");
    }

    int sidx = 0;
    for (int kb = 0; kb < NKB; ++kb) {
        // ---- produce: convert chunk kb+4 (global memory only) ----
        const bool do_conv = (kb + CONV_AHEAD < NKB);
        if (do_conv) {
            convert_chunk(w, x, kb + CONV_AHEAD, r, tid);
            __threadfence();
        }

        if (kb + 2 < NKB)
            asm volatile("cp.async.wait_group 1;" ::: "memory");
        else
            asm volatile("cp.async.wait_group 0;" ::: "memory");
        __syncthreads();   // converts done CTA-wide; stage kb visible; prior compute done

        if (tid == 0 && do_conv)
            atomicAdd(&g_cnt[kb + CONV_AHEAD], 1);

        // ---- consume-gate + prefetch chunk kb+2 ----
        if (kb + 2 < NKB) {
            if (tid == 0) {
                while (vcnt[kb + 2] < NCTA) { }
            }
            __syncthreads();
            __threadfence();
            const uint32_t sn = sbase + ((sidx + 2) % 3) * STG_BYTES;
            const size_t ko = (size_t)(kb + 2) * BK;
            #pragma unroll
            for (int i = 0; i < 4; ++i)
                cp16(sn + dOff[i], aSrc + ko + (size_t)(16 * i) * KDIM);
            #pragma unroll
            for (int i = 0; i < 8; ++i)
                cp16(sn + A_BYTES + dOff[i] + (uint32_t)(i >> 2) * 8192,
                     bSrc + ko + (size_t)(16 * i) * KDIM);
            asm volatile("cp.async.commit_group;" ::: "memory");
        }

        // ---- compute stage kb ----
        const uint32_t so = sbase + sidx * STG_BYTES;
        #pragma unroll
        for (int ks = 0; ks < 4; ++ks) {
            uint32_t a[4][4], b[4][2];
            #pragma unroll
            for (int mt = 0; mt < 4; ++mt)
                ldsm_x4(a[mt], so + aBase + mt * 2048u + swx[ks]);
            #pragma unroll
            for (int ntp = 0; ntp < 2; ++ntp) {
                uint32_t t4[4];
                ldsm_x4(t4, so + bBase + ntp * 2048u + swx[ks]);
                b[2 * ntp][0] = t4[0]; b[2 * ntp + 1][0] = t4[1];
                b[2 * ntp][1] = t4[2]; b[2 * ntp + 1][1] = t4[3];
            }
            #pragma unroll
            for (int mt = 0; mt < 4; ++mt)
                #pragma unroll
                for (int nt = 0; nt < 4; ++nt)
                    mma_f16(acc[mt][nt], a[mt], b[nt]);
        }
        sidx = (sidx == 2) ? 0 : sidx + 1;
    }

    // ---- epilogue: + bias ----
    #pragma unroll
    for (int mt = 0; mt < 4; ++mt) {
        const int row = row0 + mt * 16 + (lane >> 2);
        #pragma unroll
        for (int nt = 0; nt < 4; ++nt) {
            const int col = col0 + wn * 32 + nt * 8 + (lane & 3) * 2;
            const float2 bb = *reinterpret_cast<const float2*>(bias + col);
            float2 o0, o1;
            o0.x = acc[mt][nt][0] + bb.x;
            o0.y = acc[mt][nt][1] + bb.y;
            o1.x = acc[mt][nt][2] + bb.x;
            o1.y = acc[mt][nt][3] + bb.y;
            *reinterpret_cast<float2*>(out + (size_t)row * KDIM + col) = o0;
            *reinterpret_cast<float2*>(out + (size_t)(row + 8) * KDIM + col) = o1;
        }
    }

    // ---- reset counters for the next (graph-replayed) launch ----
    __syncthreads();
    if (tid == 0) {
        const int old = atomicAdd(&g_done, 1);
        if (old == NCTA - 1) {
            #pragma unroll
            for (int c = 0; c < NKB; ++c) g_cnt[c] = 0;
            g_done = 0;
            __threadfence();
        }
    }
}

extern "C" void kernel_launch(void* const* d_in, const int* in_sizes, int n_in,
                              void* d_out, int out_size)
{
    const float* x    = (const float*)d_in[0];   // [512, 4096]
    const float* w    = (const float*)d_in[1];   // [512, 512, 8, 8]
    const float* bias = (const float*)d_in[2];   // [512, 8] -> flat [4096]
    float* out = (float*)d_out;                  // [512, 4096]

    cudaFuncSetAttribute(octonion_fused,
                         cudaFuncAttributeMaxDynamicSharedMemorySize, SMEM_BYTES);
    dim3 grid(KDIM / 128, 512 / 64);             // (32, 8) = 256 CTAs, all co-resident
    octonion_fused<<<grid, 128, SMEM_BYTES>>>(x, w, bias, out);
}